// round 7
// baseline (speedup 1.0000x reference)
#include <cuda_runtime.h>
#include <cstdint>

#define B_SESS 4096
#define MAX_LEN 200
#define E 112
#define N_ITEMS 100000
#define LAYERS 3
#define KSPLIT 4
#define KCHUNK (B_SESS / KSPLIT)   // 1024
#define BK 32
#define NSTAGE (KCHUNK / BK)       // 32

// big_mm smem staging (uint32 units); strides conflict-free for fragment LDS.
#define AS_STRIDE 36
#define BS_STRIDE 120
#define AS_U32 (128 * AS_STRIDE)
#define BS_U32 (32 * BS_STRIDE)
#define SMEM_BYTES ((2 * AS_U32 + 2 * BS_U32) * 4)   // 67584

// small_mm smem: S tile [128][116], W^T [112][120]
#define SS_STRIDE 116
#define WS_STRIDE 120
#define SM2_BYTES ((128 * SS_STRIDE + 112 * WS_STRIDE) * 4)   // 113152

// prep kernel grid partition
#define NB_GATHER 4096
#define NB_CVT    16384
#define NB_DIAG   16
#define NB_PREP   (NB_GATHER + NB_CVT + NB_DIAG)

// Scratch
__device__ uint32_t g_Atf[(size_t)B_SESS * B_SESS];  // A in tf32 bits
__device__ uint32_t g_ttf[B_SESS * E];               // (s @ W^T) tf32 bits
__device__ float g_s[B_SESS * E];                    // layer-0 input only
__device__ float g_acc[B_SESS * E];
__device__ float g_part[KSPLIT * B_SESS * E];
__device__ float g_d[B_SESS];

// ---------------------------------------------------------------------------
// PTX helpers (plain sm_80+; no arch-'a' gating)
// ---------------------------------------------------------------------------
__device__ __forceinline__ uint32_t smem_u32(const void* p) {
    uint32_t a;
    asm("{ .reg .u64 t; cvta.to.shared.u64 t, %1; cvt.u32.u64 %0, t; }"
        : "=r"(a) : "l"(p));
    return a;
}
__device__ __forceinline__ uint32_t f2tf32(float f) {
    uint32_t u;
    asm("cvt.rn.tf32.f32 %0, %1;" : "=r"(u) : "f"(f));
    return u;
}
#define CP16(dst, src) \
    asm volatile("cp.async.cg.shared.global [%0], [%1], 16;" \
                 :: "r"(dst), "l"(src) : "memory")
#define CP_COMMIT() asm volatile("cp.async.commit_group;" ::: "memory")
#define CP_WAIT1()  asm volatile("cp.async.wait_group 1;" ::: "memory")
#define CP_WAIT0()  asm volatile("cp.async.wait_group 0;" ::: "memory")

__device__ __forceinline__ void mma_tf32(float* c, const uint32_t* a,
                                         const uint32_t* b) {
    asm volatile(
        "mma.sync.aligned.m16n8k8.row.col.f32.tf32.tf32.f32 "
        "{%0,%1,%2,%3},{%4,%5,%6,%7},{%8,%9},{%0,%1,%2,%3};"
        : "+f"(c[0]), "+f"(c[1]), "+f"(c[2]), "+f"(c[3])
        : "r"(a[0]), "r"(a[1]), "r"(a[2]), "r"(a[3]), "r"(b[0]), "r"(b[1]));
}

// ---------------------------------------------------------------------------
// 1. Prep: gather+mean (L2-bound) || cvtA (DRAM-bound) || diag, one grid.
// ---------------------------------------------------------------------------
__global__ void prep_kernel(const float* __restrict__ A,
                            const float* __restrict__ emb,
                            const int* __restrict__ items,
                            const float* __restrict__ slen,
                            const float* __restrict__ D) {
    int blk = blockIdx.x;
    int tid = threadIdx.x;

    if (blk < NB_GATHER) {                       // ---- gather + mean pool ----
        __shared__ int sidx[MAX_LEN];
        int b = blk;
        for (int i = tid; i < MAX_LEN; i += blockDim.x)
            sidx[i] = items[(size_t)b * MAX_LEN + i];
        __syncthreads();
        if (tid < E) {
            float acc = 0.0f;
            #pragma unroll 4
            for (int t = 0; t < MAX_LEN; ++t) {
                int idx = sidx[t];
                if (idx > 0 && idx <= N_ITEMS)
                    acc += emb[((size_t)(idx - 1)) * E + tid];
            }
            float v = acc / slen[b];
            g_s[(size_t)b * E + tid] = v;
            g_acc[(size_t)b * E + tid] = v;
        }
    } else if (blk < NB_GATHER + NB_CVT) {       // ---- A -> tf32 bits ----
        size_t i = (((size_t)(blk - NB_GATHER)) * 256 + tid) * 4;
        float4 v = *reinterpret_cast<const float4*>(A + i);
        uint4 u = make_uint4(f2tf32(v.x), f2tf32(v.y), f2tf32(v.z), f2tf32(v.w));
        *reinterpret_cast<uint4*>(g_Atf + i) = u;
    } else {                                     // ---- diag(D) ----
        int i = (blk - NB_GATHER - NB_CVT) * 256 + tid;
        if (i < B_SESS)
            g_d[i] = D[(size_t)i * B_SESS + i];
    }
}

// ---------------------------------------------------------------------------
// 2. small GEMM on tensor cores, with fused split-K reduce/norm prologue.
//    grid 32 x 256 thr. M=128/CTA, N=112, K=112.
//    first=1: S tile from g_s.
//    first=0: S tile = d * sum_k part[k]  (also: acc += normalized(S row)).
// ---------------------------------------------------------------------------
__global__ void __launch_bounds__(256)
small_mm_tc(const float* __restrict__ W, int first) {
    extern __shared__ uint32_t sm2[];
    uint32_t* Ss = sm2;                          // [128][SS_STRIDE]
    uint32_t* Wt = sm2 + 128 * SS_STRIDE;        // [112][WS_STRIDE] (k-major)

    const int tid = threadIdx.x;
    const int lane = tid & 31;
    const int wid = tid >> 5;
    const int wm = wid & 3;
    const int wn = wid >> 2;
    const int g = lane >> 2;
    const int t = lane & 3;
    const int row0 = blockIdx.x * 128;

    if (first) {
        for (int idx = tid; idx < 128 * E; idx += 256) {
            int r = idx / E, c = idx % E;
            Ss[r * SS_STRIDE + c] = f2tf32(g_s[(size_t)(row0 + r) * E + c]);
        }
    } else {
        // fused reduce_norm for the previous layer's big_mm output (my rows)
        #pragma unroll 1
        for (int it = 0; it < 16; ++it) {
            int rr = it * 8 + wid;               // local row 0..127
            int r = row0 + rr;
            float4 v = make_float4(0.f, 0.f, 0.f, 0.f);
            if (lane < E / 4) {
                #pragma unroll
                for (int c = 0; c < KSPLIT; ++c) {
                    float4 p = *reinterpret_cast<const float4*>(
                        &g_part[(size_t)c * B_SESS * E + (size_t)r * E + lane * 4]);
                    v.x += p.x; v.y += p.y; v.z += p.z; v.w += p.w;
                }
                float d = g_d[r];
                v.x *= d; v.y *= d; v.z *= d; v.w *= d;
            }
            float ss = v.x * v.x + v.y * v.y + v.z * v.z + v.w * v.w;
            #pragma unroll
            for (int o = 16; o; o >>= 1)
                ss += __shfl_xor_sync(0xffffffffu, ss, o);
            float f = 1.0f / fmaxf(sqrtf(ss), 1e-12f);
            if (lane < E / 4) {
                float4* arow = reinterpret_cast<float4*>(g_acc + (size_t)r * E);
                float4 a = arow[lane];
                a.x = fmaf(v.x, f, a.x);
                a.y = fmaf(v.y, f, a.y);
                a.z = fmaf(v.z, f, a.z);
                a.w = fmaf(v.w, f, a.w);
                arow[lane] = a;
                // un-normalized value feeds the next layer (torch semantics)
                uint32_t* srow = &Ss[rr * SS_STRIDE + lane * 4];
                srow[0] = f2tf32(v.x);
                srow[1] = f2tf32(v.y);
                srow[2] = f2tf32(v.z);
                srow[3] = f2tf32(v.w);
            }
        }
    }
    for (int idx = tid; idx < E * E; idx += 256) {
        int o = idx / E, i = idx % E;            // W[o][i] -> Wt[i][o]
        Wt[i * WS_STRIDE + o] = f2tf32(W[(size_t)o * E + i]);
    }
    __syncthreads();

    float acc[2][7][4];
    #pragma unroll
    for (int i = 0; i < 2; ++i)
        #pragma unroll
        for (int j = 0; j < 7; ++j)
            #pragma unroll
            for (int k = 0; k < 4; ++k) acc[i][j][k] = 0.0f;

    #pragma unroll
    for (int ks = 0; ks < 14; ++ks) {
        uint32_t a[2][4], b[7][2];
        #pragma unroll
        for (int i = 0; i < 2; ++i) {
            int r = wm * 32 + i * 16 + g;
            int c = ks * 8 + t;
            a[i][0] = Ss[r * SS_STRIDE + c];
            a[i][1] = Ss[(r + 8) * SS_STRIDE + c];
            a[i][2] = Ss[r * SS_STRIDE + c + 4];
            a[i][3] = Ss[(r + 8) * SS_STRIDE + c + 4];
        }
        #pragma unroll
        for (int j = 0; j < 7; ++j) {
            int n = wn * 56 + j * 8 + g;
            int r = ks * 8 + t;
            b[j][0] = Wt[r * WS_STRIDE + n];
            b[j][1] = Wt[(r + 4) * WS_STRIDE + n];
        }
        #pragma unroll
        for (int i = 0; i < 2; ++i)
            #pragma unroll
            for (int j = 0; j < 7; ++j)
                mma_tf32(acc[i][j], a[i], b[j]);
    }

    #pragma unroll
    for (int i = 0; i < 2; ++i) {
        int r = row0 + wm * 32 + i * 16 + g;
        #pragma unroll
        for (int j = 0; j < 7; ++j) {
            int n = wn * 56 + j * 8 + 2 * t;
            *reinterpret_cast<uint2*>(&g_ttf[(size_t)r * E + n]) =
                make_uint2(f2tf32(acc[i][j][0]), f2tf32(acc[i][j][1]));
            *reinterpret_cast<uint2*>(&g_ttf[(size_t)(r + 8) * E + n]) =
                make_uint2(f2tf32(acc[i][j][2]), f2tf32(acc[i][j][3]));
        }
    }
}

// ---------------------------------------------------------------------------
// 3. Big tensor-core GEMM: part[split] = A[:, kc] @ t[kc, :]
// ---------------------------------------------------------------------------
__global__ void __launch_bounds__(256)
big_mm_mma() {
    extern __shared__ uint32_t smem[];
    uint32_t* As = smem;                   // [2][128][AS_STRIDE]
    uint32_t* Bs = smem + 2 * AS_U32;      // [2][32][BS_STRIDE]

    const int tid = threadIdx.x;
    const int lane = tid & 31;
    const int wid = tid >> 5;
    const int wm = wid & 3;
    const int wn = wid >> 2;
    const int g = lane >> 2;
    const int t = lane & 3;
    const int row0 = blockIdx.x * 128;
    const int kbase = blockIdx.y * KCHUNK;

    float acc[2][7][4];
    #pragma unroll
    for (int i = 0; i < 2; ++i)
        #pragma unroll
        for (int j = 0; j < 7; ++j)
            #pragma unroll
            for (int k = 0; k < 4; ++k) acc[i][j][k] = 0.0f;

    auto stage = [&](int buf, int k0) {
        uint32_t* Ab = As + buf * AS_U32;
        uint32_t* Bb = Bs + buf * BS_U32;
        #pragma unroll
        for (int j = 0; j < 4; ++j) {
            int c = tid + j * 256;
            int r = c >> 3, cc = c & 7;
            uint32_t dst = smem_u32(&Ab[r * AS_STRIDE + cc * 4]);
            CP16(dst, &g_Atf[(size_t)(row0 + r) * B_SESS + k0 + cc * 4]);
        }
        #pragma unroll
        for (int j = 0; j < 4; ++j) {
            int c = tid + j * 256;
            if (c < 896) {
                int r = c / 28, cc = c % 28;
                uint32_t dst = smem_u32(&Bb[r * BS_STRIDE + cc * 4]);
                CP16(dst, &g_ttf[(size_t)(k0 + r) * E + cc * 4]);
            }
        }
    };

    auto compute = [&](int buf) {
        const uint32_t* A_ = As + buf * AS_U32;
        const uint32_t* B_ = Bs + buf * BS_U32;
        #pragma unroll
        for (int ks = 0; ks < 4; ++ks) {
            uint32_t a[2][4], b[7][2];
            #pragma unroll
            for (int i = 0; i < 2; ++i) {
                int r = wm * 32 + i * 16 + g;
                int c = ks * 8 + t;
                a[i][0] = A_[r * AS_STRIDE + c];
                a[i][1] = A_[(r + 8) * AS_STRIDE + c];
                a[i][2] = A_[r * AS_STRIDE + c + 4];
                a[i][3] = A_[(r + 8) * AS_STRIDE + c + 4];
            }
            #pragma unroll
            for (int j = 0; j < 7; ++j) {
                int n = wn * 56 + j * 8 + g;
                int r = ks * 8 + t;
                b[j][0] = B_[r * BS_STRIDE + n];
                b[j][1] = B_[(r + 4) * BS_STRIDE + n];
            }
            #pragma unroll
            for (int i = 0; i < 2; ++i)
                #pragma unroll
                for (int j = 0; j < 7; ++j)
                    mma_tf32(acc[i][j], a[i], b[j]);
        }
    };

    stage(0, kbase);
    CP_COMMIT();
    for (int s = 0; s < NSTAGE; ++s) {
        if (s + 1 < NSTAGE) {
            stage((s + 1) & 1, kbase + (s + 1) * BK);
            CP_COMMIT();
            CP_WAIT1();
        } else {
            CP_WAIT0();
        }
        __syncthreads();
        compute(s & 1);
        __syncthreads();
    }

    float* part = g_part + (size_t)blockIdx.y * B_SESS * E;
    #pragma unroll
    for (int i = 0; i < 2; ++i) {
        int r = row0 + wm * 32 + i * 16 + g;
        #pragma unroll
        for (int j = 0; j < 7; ++j) {
            int n = wn * 56 + j * 8 + 2 * t;
            *reinterpret_cast<float2*>(&part[(size_t)r * E + n]) =
                make_float2(acc[i][j][0], acc[i][j][1]);
            *reinterpret_cast<float2*>(&part[(size_t)(r + 8) * E + n]) =
                make_float2(acc[i][j][2], acc[i][j][3]);
        }
    }
}

// ---------------------------------------------------------------------------
// 4. Final: split-K reduce + diag scale + L2-normalize + acc + out.
//    One warp per row; block = 8 warps; grid = 512.
// ---------------------------------------------------------------------------
__global__ void reduce_norm_final(float* __restrict__ out) {
    int warp = threadIdx.x >> 5;
    int lane = threadIdx.x & 31;
    int r = blockIdx.x * 8 + warp;

    float4 v = make_float4(0.f, 0.f, 0.f, 0.f);
    if (lane < E / 4) {
        #pragma unroll
        for (int c = 0; c < KSPLIT; ++c) {
            float4 p = *reinterpret_cast<const float4*>(
                &g_part[(size_t)c * B_SESS * E + (size_t)r * E + lane * 4]);
            v.x += p.x; v.y += p.y; v.z += p.z; v.w += p.w;
        }
        float d = g_d[r];
        v.x *= d; v.y *= d; v.z *= d; v.w *= d;
    }
    float ss = v.x * v.x + v.y * v.y + v.z * v.z + v.w * v.w;
    #pragma unroll
    for (int o = 16; o; o >>= 1) ss += __shfl_xor_sync(0xffffffffu, ss, o);
    float f = 1.0f / fmaxf(sqrtf(ss), 1e-12f);
    if (lane < E / 4) {
        const float4* arow = reinterpret_cast<const float4*>(g_acc + (size_t)r * E);
        float4 a = arow[lane];
        float4 o4;
        o4.x = fmaf(v.x, f, a.x) * 0.25f;
        o4.y = fmaf(v.y, f, a.y) * 0.25f;
        o4.z = fmaf(v.z, f, a.z) * 0.25f;
        o4.w = fmaf(v.w, f, a.w) * 0.25f;
        *reinterpret_cast<float4*>(&out[(size_t)r * E + lane * 4]) = o4;
    }
}

// ---------------------------------------------------------------------------
extern "C" void kernel_launch(void* const* d_in, const int* in_sizes, int n_in,
                              void* d_out, int out_size) {
    const float* emb   = (const float*)d_in[0];     // [100000,112]
    const float* D     = (const float*)d_in[1];     // [4096,4096]
    const float* A     = (const float*)d_in[2];     // [4096,4096]
    const float* slen  = (const float*)d_in[3];     // [4096,1]
    const float* Ws    = (const float*)d_in[4];     // [3,112,112]
    const int*   items = (const int*)d_in[5];       // [4096,200] int32
    float* out = (float*)d_out;

    cudaFuncSetAttribute(big_mm_mma, cudaFuncAttributeMaxDynamicSharedMemorySize,
                         SMEM_BYTES);
    cudaFuncSetAttribute(small_mm_tc, cudaFuncAttributeMaxDynamicSharedMemorySize,
                         SM2_BYTES);

    prep_kernel<<<NB_PREP, 256>>>(A, emb, items, slen, D);

    for (int l = 0; l < LAYERS; ++l) {
        small_mm_tc<<<32, 256, SM2_BYTES>>>(Ws + (size_t)l * E * E, l == 0);
        big_mm_mma<<<dim3(B_SESS / 128, KSPLIT), 256, SMEM_BYTES>>>();
    }
    reduce_norm_final<<<B_SESS / 8, 256>>>(out);
}

// round 8
// speedup vs baseline: 1.2350x; 1.2350x over previous
#include <cuda_runtime.h>
#include <cstdint>

#define B_SESS 4096
#define MAX_LEN 200
#define E 112
#define N_ITEMS 100000
#define LAYERS 3
#define KSPLIT 8
#define KCHUNK (B_SESS / KSPLIT)   // 512
#define BK 32
#define NSTAGE (KCHUNK / BK)       // 16

// big_mm smem staging (uint32 units); strides conflict-free for fragment LDS.
#define AS_STRIDE 36
#define BS_STRIDE 120
#define AS_U32 (128 * AS_STRIDE)
#define BS_U32 (32 * BS_STRIDE)
#define SMEM_BYTES ((2 * AS_U32 + 2 * BS_U32) * 4)   // 67584

// small_mm smem: S tile [32][116], W^T [112][120]
#define SS_STRIDE 116
#define WS_STRIDE 120
#define SM2_BYTES ((32 * SS_STRIDE + 112 * WS_STRIDE) * 4)   // 68608

// prep kernel grid partition
#define NB_GATHER 4096
#define NB_CVT    16384
#define NB_DIAG   16
#define NB_PREP   (NB_GATHER + NB_CVT + NB_DIAG)

// Scratch
__device__ uint32_t g_Atf[(size_t)B_SESS * B_SESS];  // A in tf32 bits
__device__ uint32_t g_ttf[B_SESS * E];               // (s @ W^T) tf32 bits
__device__ float g_s[B_SESS * E];
__device__ float g_acc[B_SESS * E];
__device__ float g_part[KSPLIT * B_SESS * E];
__device__ float g_d[B_SESS];

// ---------------------------------------------------------------------------
// PTX helpers (plain sm_80+; no arch-'a' gating)
// ---------------------------------------------------------------------------
__device__ __forceinline__ uint32_t smem_u32(const void* p) {
    uint32_t a;
    asm("{ .reg .u64 t; cvta.to.shared.u64 t, %1; cvt.u32.u64 %0, t; }"
        : "=r"(a) : "l"(p));
    return a;
}
__device__ __forceinline__ uint32_t f2tf32(float f) {
    uint32_t u;
    asm("cvt.rn.tf32.f32 %0, %1;" : "=r"(u) : "f"(f));
    return u;
}
#define CP16(dst, src) \
    asm volatile("cp.async.cg.shared.global [%0], [%1], 16;" \
                 :: "r"(dst), "l"(src) : "memory")
#define CP_COMMIT() asm volatile("cp.async.commit_group;" ::: "memory")
#define CP_WAIT1()  asm volatile("cp.async.wait_group 1;" ::: "memory")
#define CP_WAIT0()  asm volatile("cp.async.wait_group 0;" ::: "memory")

__device__ __forceinline__ void mma_tf32(float* c, const uint32_t* a,
                                         const uint32_t* b) {
    asm volatile(
        "mma.sync.aligned.m16n8k8.row.col.f32.tf32.tf32.f32 "
        "{%0,%1,%2,%3},{%4,%5,%6,%7},{%8,%9},{%0,%1,%2,%3};"
        : "+f"(c[0]), "+f"(c[1]), "+f"(c[2]), "+f"(c[3])
        : "r"(a[0]), "r"(a[1]), "r"(a[2]), "r"(a[3]), "r"(b[0]), "r"(b[1]));
}

// ---------------------------------------------------------------------------
// 1. Prep: gather+mean (2-way split) || cvtA || diag, one grid of 256-thr CTAs.
// ---------------------------------------------------------------------------
__global__ void prep_kernel(const float* __restrict__ A,
                            const float* __restrict__ emb,
                            const int* __restrict__ items,
                            const float* __restrict__ slen,
                            const float* __restrict__ D) {
    int blk = blockIdx.x;
    int tid = threadIdx.x;

    if (blk < NB_GATHER) {                       // ---- gather + mean pool ----
        __shared__ int sidx[MAX_LEN];
        __shared__ float partial[E];
        int b = blk;
        for (int i = tid; i < MAX_LEN; i += blockDim.x)
            sidx[i] = items[(size_t)b * MAX_LEN + i];
        __syncthreads();
        float acc = 0.0f;
        int col = (tid < E) ? tid : tid - E;     // two halves of 112 cols
        if (tid < 2 * E) {
            int t0 = (tid < E) ? 0 : MAX_LEN / 2;
            int t1 = t0 + MAX_LEN / 2;
            #pragma unroll 4
            for (int t = t0; t < t1; ++t) {
                int idx = sidx[t];
                if (idx > 0 && idx <= N_ITEMS)
                    acc += emb[((size_t)(idx - 1)) * E + col];
            }
        }
        if (tid >= E && tid < 2 * E) partial[col] = acc;
        __syncthreads();
        if (tid < E) {
            float v = (acc + partial[tid]) / slen[b];
            g_s[(size_t)b * E + tid] = v;
            g_acc[(size_t)b * E + tid] = v;
        }
    } else if (blk < NB_GATHER + NB_CVT) {       // ---- A -> tf32 bits ----
        size_t i = (((size_t)(blk - NB_GATHER)) * 256 + tid) * 4;
        float4 v = *reinterpret_cast<const float4*>(A + i);
        uint4 u = make_uint4(f2tf32(v.x), f2tf32(v.y), f2tf32(v.z), f2tf32(v.w));
        *reinterpret_cast<uint4*>(g_Atf + i) = u;
    } else {                                     // ---- diag(D) ----
        int i = (blk - NB_GATHER - NB_CVT) * 256 + tid;
        if (i < B_SESS)
            g_d[i] = D[(size_t)i * B_SESS + i];
    }
}

// ---------------------------------------------------------------------------
// 2. small GEMM on tensor cores: g_ttf = tf32(g_s @ W^T)
//    grid 128 x 128 thr (4 warps: 2(M) x 2(N)). M=32/CTA, N=112, K=112.
// ---------------------------------------------------------------------------
__global__ void __launch_bounds__(128)
small_mm_tc(const float* __restrict__ W) {
    extern __shared__ uint32_t sm2[];
    uint32_t* Ss = sm2;                          // [32][SS_STRIDE]
    uint32_t* Wt = sm2 + 32 * SS_STRIDE;         // [112][WS_STRIDE] (k-major)

    const int tid = threadIdx.x;
    const int lane = tid & 31;
    const int wid = tid >> 5;
    const int wm = wid & 1;                      // 2 M-strips of 16 rows
    const int wn = wid >> 1;                     // 2 N-strips of 56 cols
    const int g = lane >> 2;
    const int t = lane & 3;
    const int row0 = blockIdx.x * 32;

    // stage S tile (32 x 112) as tf32
    for (int idx = tid; idx < 32 * (E / 4); idx += 128) {
        int r = idx / (E / 4), c4 = idx % (E / 4);
        float4 v = *reinterpret_cast<const float4*>(
            &g_s[(size_t)(row0 + r) * E + c4 * 4]);
        uint32_t* dst = &Ss[r * SS_STRIDE + c4 * 4];
        dst[0] = f2tf32(v.x); dst[1] = f2tf32(v.y);
        dst[2] = f2tf32(v.z); dst[3] = f2tf32(v.w);
    }
    // stage W^T (k-major) as tf32: W[o][i] -> Wt[i][o]
    for (int idx = tid; idx < E * (E / 4); idx += 128) {
        int o = idx / (E / 4), i4 = idx % (E / 4);
        float4 v = *reinterpret_cast<const float4*>(&W[(size_t)o * E + i4 * 4]);
        Wt[(i4 * 4 + 0) * WS_STRIDE + o] = f2tf32(v.x);
        Wt[(i4 * 4 + 1) * WS_STRIDE + o] = f2tf32(v.y);
        Wt[(i4 * 4 + 2) * WS_STRIDE + o] = f2tf32(v.z);
        Wt[(i4 * 4 + 3) * WS_STRIDE + o] = f2tf32(v.w);
    }
    __syncthreads();

    float acc[7][4];
    #pragma unroll
    for (int j = 0; j < 7; ++j)
        #pragma unroll
        for (int k = 0; k < 4; ++k) acc[j][k] = 0.0f;

    #pragma unroll
    for (int ks = 0; ks < 14; ++ks) {
        uint32_t a[4], b[7][2];
        {
            int r = wm * 16 + g;
            int c = ks * 8 + t;
            a[0] = Ss[r * SS_STRIDE + c];
            a[1] = Ss[(r + 8) * SS_STRIDE + c];
            a[2] = Ss[r * SS_STRIDE + c + 4];
            a[3] = Ss[(r + 8) * SS_STRIDE + c + 4];
        }
        #pragma unroll
        for (int j = 0; j < 7; ++j) {
            int n = wn * 56 + j * 8 + g;
            int r = ks * 8 + t;
            b[j][0] = Wt[r * WS_STRIDE + n];
            b[j][1] = Wt[(r + 4) * WS_STRIDE + n];
        }
        #pragma unroll
        for (int j = 0; j < 7; ++j)
            mma_tf32(acc[j], a, b[j]);
    }

    {
        int r = row0 + wm * 16 + g;
        #pragma unroll
        for (int j = 0; j < 7; ++j) {
            int n = wn * 56 + j * 8 + 2 * t;
            *reinterpret_cast<uint2*>(&g_ttf[(size_t)r * E + n]) =
                make_uint2(f2tf32(acc[j][0]), f2tf32(acc[j][1]));
            *reinterpret_cast<uint2*>(&g_ttf[(size_t)(r + 8) * E + n]) =
                make_uint2(f2tf32(acc[j][2]), f2tf32(acc[j][3]));
        }
    }
}

// ---------------------------------------------------------------------------
// 3. Big tensor-core GEMM: part[split] = A[:, kc] @ t[kc, :]
// ---------------------------------------------------------------------------
__global__ void __launch_bounds__(256)
big_mm_mma() {
    extern __shared__ uint32_t smem[];
    uint32_t* As = smem;                   // [2][128][AS_STRIDE]
    uint32_t* Bs = smem + 2 * AS_U32;      // [2][32][BS_STRIDE]

    const int tid = threadIdx.x;
    const int lane = tid & 31;
    const int wid = tid >> 5;
    const int wm = wid & 3;
    const int wn = wid >> 2;
    const int g = lane >> 2;
    const int t = lane & 3;
    const int row0 = blockIdx.x * 128;
    const int kbase = blockIdx.y * KCHUNK;

    float acc[2][7][4];
    #pragma unroll
    for (int i = 0; i < 2; ++i)
        #pragma unroll
        for (int j = 0; j < 7; ++j)
            #pragma unroll
            for (int k = 0; k < 4; ++k) acc[i][j][k] = 0.0f;

    auto stage = [&](int buf, int k0) {
        uint32_t* Ab = As + buf * AS_U32;
        uint32_t* Bb = Bs + buf * BS_U32;
        #pragma unroll
        for (int j = 0; j < 4; ++j) {
            int c = tid + j * 256;
            int r = c >> 3, cc = c & 7;
            uint32_t dst = smem_u32(&Ab[r * AS_STRIDE + cc * 4]);
            CP16(dst, &g_Atf[(size_t)(row0 + r) * B_SESS + k0 + cc * 4]);
        }
        #pragma unroll
        for (int j = 0; j < 4; ++j) {
            int c = tid + j * 256;
            if (c < 896) {
                int r = c / 28, cc = c % 28;
                uint32_t dst = smem_u32(&Bb[r * BS_STRIDE + cc * 4]);
                CP16(dst, &g_ttf[(size_t)(k0 + r) * E + cc * 4]);
            }
        }
    };

    auto compute = [&](int buf) {
        const uint32_t* A_ = As + buf * AS_U32;
        const uint32_t* B_ = Bs + buf * BS_U32;
        #pragma unroll
        for (int ks = 0; ks < 4; ++ks) {
            uint32_t a[2][4], b[7][2];
            #pragma unroll
            for (int i = 0; i < 2; ++i) {
                int r = wm * 32 + i * 16 + g;
                int c = ks * 8 + t;
                a[i][0] = A_[r * AS_STRIDE + c];
                a[i][1] = A_[(r + 8) * AS_STRIDE + c];
                a[i][2] = A_[r * AS_STRIDE + c + 4];
                a[i][3] = A_[(r + 8) * AS_STRIDE + c + 4];
            }
            #pragma unroll
            for (int j = 0; j < 7; ++j) {
                int n = wn * 56 + j * 8 + g;
                int r = ks * 8 + t;
                b[j][0] = B_[r * BS_STRIDE + n];
                b[j][1] = B_[(r + 4) * BS_STRIDE + n];
            }
            #pragma unroll
            for (int i = 0; i < 2; ++i)
                #pragma unroll
                for (int j = 0; j < 7; ++j)
                    mma_tf32(acc[i][j], a[i], b[j]);
        }
    };

    stage(0, kbase);
    CP_COMMIT();
    for (int s = 0; s < NSTAGE; ++s) {
        if (s + 1 < NSTAGE) {
            stage((s + 1) & 1, kbase + (s + 1) * BK);
            CP_COMMIT();
            CP_WAIT1();
        } else {
            CP_WAIT0();
        }
        __syncthreads();
        compute(s & 1);
        __syncthreads();
    }

    float* part = g_part + (size_t)blockIdx.y * B_SESS * E;
    #pragma unroll
    for (int i = 0; i < 2; ++i) {
        int r = row0 + wm * 32 + i * 16 + g;
        #pragma unroll
        for (int j = 0; j < 7; ++j) {
            int n = wn * 56 + j * 8 + 2 * t;
            *reinterpret_cast<float2*>(&part[(size_t)r * E + n]) =
                make_float2(acc[i][j][0], acc[i][j][1]);
            *reinterpret_cast<float2*>(&part[(size_t)(r + 8) * E + n]) =
                make_float2(acc[i][j][2], acc[i][j][3]);
        }
    }
}

// ---------------------------------------------------------------------------
// 4. Fused: split-K reduce + diag scale + L2-normalize + acc (+ final out)
//    One warp per row; block = 8 warps; grid = 512.
// ---------------------------------------------------------------------------
__global__ void reduce_norm_kernel(float* __restrict__ out, int last) {
    int warp = threadIdx.x >> 5;
    int lane = threadIdx.x & 31;
    int r = blockIdx.x * 8 + warp;

    float4 v = make_float4(0.f, 0.f, 0.f, 0.f);
    if (lane < E / 4) {
        #pragma unroll
        for (int c = 0; c < KSPLIT; ++c) {
            float4 p = *reinterpret_cast<const float4*>(
                &g_part[(size_t)c * B_SESS * E + (size_t)r * E + lane * 4]);
            v.x += p.x; v.y += p.y; v.z += p.z; v.w += p.w;
        }
        float d = g_d[r];
        v.x *= d; v.y *= d; v.z *= d; v.w *= d;
        *reinterpret_cast<float4*>(&g_s[(size_t)r * E + lane * 4]) = v;
    }
    float ss = v.x * v.x + v.y * v.y + v.z * v.z + v.w * v.w;
    #pragma unroll
    for (int o = 16; o; o >>= 1) ss += __shfl_xor_sync(0xffffffffu, ss, o);
    float f = 1.0f / fmaxf(sqrtf(ss), 1e-12f);
    if (lane < E / 4) {
        float4* arow = reinterpret_cast<float4*>(g_acc + (size_t)r * E);
        float4 a = arow[lane];
        a.x = fmaf(v.x, f, a.x);
        a.y = fmaf(v.y, f, a.y);
        a.z = fmaf(v.z, f, a.z);
        a.w = fmaf(v.w, f, a.w);
        arow[lane] = a;
        if (last) {
            float4 o4 = make_float4(a.x * 0.25f, a.y * 0.25f,
                                    a.z * 0.25f, a.w * 0.25f);
            *reinterpret_cast<float4*>(&out[(size_t)r * E + lane * 4]) = o4;
        }
    }
}

// ---------------------------------------------------------------------------
extern "C" void kernel_launch(void* const* d_in, const int* in_sizes, int n_in,
                              void* d_out, int out_size) {
    const float* emb   = (const float*)d_in[0];     // [100000,112]
    const float* D     = (const float*)d_in[1];     // [4096,4096]
    const float* A     = (const float*)d_in[2];     // [4096,4096]
    const float* slen  = (const float*)d_in[3];     // [4096,1]
    const float* Ws    = (const float*)d_in[4];     // [3,112,112]
    const int*   items = (const int*)d_in[5];       // [4096,200] int32
    float* out = (float*)d_out;

    cudaFuncSetAttribute(big_mm_mma, cudaFuncAttributeMaxDynamicSharedMemorySize,
                         SMEM_BYTES);
    cudaFuncSetAttribute(small_mm_tc, cudaFuncAttributeMaxDynamicSharedMemorySize,
                         SM2_BYTES);

    prep_kernel<<<NB_PREP, 256>>>(A, emb, items, slen, D);

    for (int l = 0; l < LAYERS; ++l) {
        small_mm_tc<<<128, 128, SM2_BYTES>>>(Ws + (size_t)l * E * E);
        big_mm_mma<<<dim3(B_SESS / 128, KSPLIT), 256, SMEM_BYTES>>>();
        reduce_norm_kernel<<<B_SESS / 8, 256>>>(out, l == LAYERS - 1);
    }
}

// round 9
// speedup vs baseline: 1.3654x; 1.1056x over previous
#include <cuda_runtime.h>
#include <cstdint>

#define B_SESS 4096
#define MAX_LEN 200
#define E 112
#define N_ITEMS 100000
#define LAYERS 3
#define KSPLIT 8
#define KCHUNK (B_SESS / KSPLIT)   // 512
#define BK 32
#define NSTAGE (KCHUNK / BK)       // 16

// big_mm smem staging (uint32 units); strides conflict-free for fragment LDS.
#define AS_STRIDE 36
#define BS_STRIDE 120
#define AS_U32 (128 * AS_STRIDE)
#define BS_U32 (32 * BS_STRIDE)
#define SMEM_BYTES ((2 * AS_U32 + 2 * BS_U32) * 4)   // 67584

// small_mm smem: S tile [32][116], W^T [112][120]
#define SS_STRIDE 116
#define WS_STRIDE 120
#define SM2_BYTES ((32 * SS_STRIDE + 112 * WS_STRIDE) * 4)   // 68608

// prep kernel grid partition (448 threads/CTA)
#define NB_GATHER 4096
#define NB_DIAG   10                 // ceil(4096/448)
#define NB_PREP   (NB_GATHER + NB_DIAG)

// Scratch
__device__ uint32_t g_ttf[B_SESS * E];               // (s @ W^T) tf32 bits
__device__ float g_s[B_SESS * E];
__device__ float g_acc[B_SESS * E];
__device__ float g_part[KSPLIT * B_SESS * E];
__device__ float g_d[B_SESS];

// ---------------------------------------------------------------------------
// PTX helpers (plain sm_80+; no arch-'a' gating)
// ---------------------------------------------------------------------------
__device__ __forceinline__ uint32_t smem_u32(const void* p) {
    uint32_t a;
    asm("{ .reg .u64 t; cvta.to.shared.u64 t, %1; cvt.u32.u64 %0, t; }"
        : "=r"(a) : "l"(p));
    return a;
}
__device__ __forceinline__ uint32_t f2tf32(float f) {
    uint32_t u;
    asm("cvt.rn.tf32.f32 %0, %1;" : "=r"(u) : "f"(f));
    return u;
}
#define CP16(dst, src) \
    asm volatile("cp.async.cg.shared.global [%0], [%1], 16;" \
                 :: "r"(dst), "l"(src) : "memory")
#define CP_COMMIT() asm volatile("cp.async.commit_group;" ::: "memory")
#define CP_WAIT1()  asm volatile("cp.async.wait_group 1;" ::: "memory")
#define CP_WAIT0()  asm volatile("cp.async.wait_group 0;" ::: "memory")

__device__ __forceinline__ void mma_tf32(float* c, const uint32_t* a,
                                         const uint32_t* b) {
    asm volatile(
        "mma.sync.aligned.m16n8k8.row.col.f32.tf32.tf32.f32 "
        "{%0,%1,%2,%3},{%4,%5,%6,%7},{%8,%9},{%0,%1,%2,%3};"
        : "+f"(c[0]), "+f"(c[1]), "+f"(c[2]), "+f"(c[3])
        : "r"(a[0]), "r"(a[1]), "r"(a[2]), "r"(a[3]), "r"(b[0]), "r"(b[1]));
}

// ---------------------------------------------------------------------------
// 1. Prep: gather+mean (4-way time split, 448 thr) || diag.
// ---------------------------------------------------------------------------
__global__ void __launch_bounds__(448)
prep_kernel(const float* __restrict__ emb,
            const int* __restrict__ items,
            const float* __restrict__ slen,
            const float* __restrict__ D) {
    int blk = blockIdx.x;
    int tid = threadIdx.x;

    if (blk < NB_GATHER) {                       // ---- gather + mean pool ----
        __shared__ int sidx[MAX_LEN];
        __shared__ float partial[3][E];
        int b = blk;
        for (int i = tid; i < MAX_LEN; i += blockDim.x)
            sidx[i] = items[(size_t)b * MAX_LEN + i];
        __syncthreads();
        int q = tid / E;                         // quarter 0..3
        int col = tid - q * E;
        float acc = 0.0f;
        {
            int t0 = q * (MAX_LEN / 4);
            int t1 = t0 + (MAX_LEN / 4);
            #pragma unroll 5
            for (int t = t0; t < t1; ++t) {
                int idx = sidx[t];
                if (idx > 0 && idx <= N_ITEMS)
                    acc += emb[((size_t)(idx - 1)) * E + col];
            }
        }
        if (q > 0) partial[q - 1][col] = acc;
        __syncthreads();
        if (q == 0) {
            float v = (acc + partial[0][col] + partial[1][col] +
                       partial[2][col]) / slen[b];
            g_s[(size_t)b * E + col] = v;
            g_acc[(size_t)b * E + col] = v;
        }
    } else {                                     // ---- diag(D) ----
        int i = (blk - NB_GATHER) * 448 + tid;
        if (i < B_SESS)
            g_d[i] = D[(size_t)i * B_SESS + i];
    }
}

// ---------------------------------------------------------------------------
// 2. small GEMM on tensor cores: g_ttf = tf32(g_s @ W^T)
//    grid 128 x 128 thr (4 warps: 2(M) x 2(N)). M=32/CTA, N=112, K=112.
// ---------------------------------------------------------------------------
__global__ void __launch_bounds__(128)
small_mm_tc(const float* __restrict__ W) {
    extern __shared__ uint32_t sm2[];
    uint32_t* Ss = sm2;                          // [32][SS_STRIDE]
    uint32_t* Wt = sm2 + 32 * SS_STRIDE;         // [112][WS_STRIDE] (k-major)

    const int tid = threadIdx.x;
    const int lane = tid & 31;
    const int wid = tid >> 5;
    const int wm = wid & 1;
    const int wn = wid >> 1;
    const int g = lane >> 2;
    const int t = lane & 3;
    const int row0 = blockIdx.x * 32;

    for (int idx = tid; idx < 32 * (E / 4); idx += 128) {
        int r = idx / (E / 4), c4 = idx % (E / 4);
        float4 v = *reinterpret_cast<const float4*>(
            &g_s[(size_t)(row0 + r) * E + c4 * 4]);
        uint32_t* dst = &Ss[r * SS_STRIDE + c4 * 4];
        dst[0] = f2tf32(v.x); dst[1] = f2tf32(v.y);
        dst[2] = f2tf32(v.z); dst[3] = f2tf32(v.w);
    }
    for (int idx = tid; idx < E * (E / 4); idx += 128) {
        int o = idx / (E / 4), i4 = idx % (E / 4);
        float4 v = *reinterpret_cast<const float4*>(&W[(size_t)o * E + i4 * 4]);
        Wt[(i4 * 4 + 0) * WS_STRIDE + o] = f2tf32(v.x);
        Wt[(i4 * 4 + 1) * WS_STRIDE + o] = f2tf32(v.y);
        Wt[(i4 * 4 + 2) * WS_STRIDE + o] = f2tf32(v.z);
        Wt[(i4 * 4 + 3) * WS_STRIDE + o] = f2tf32(v.w);
    }
    __syncthreads();

    float acc[7][4];
    #pragma unroll
    for (int j = 0; j < 7; ++j)
        #pragma unroll
        for (int k = 0; k < 4; ++k) acc[j][k] = 0.0f;

    #pragma unroll
    for (int ks = 0; ks < 14; ++ks) {
        uint32_t a[4], b[7][2];
        {
            int r = wm * 16 + g;
            int c = ks * 8 + t;
            a[0] = Ss[r * SS_STRIDE + c];
            a[1] = Ss[(r + 8) * SS_STRIDE + c];
            a[2] = Ss[r * SS_STRIDE + c + 4];
            a[3] = Ss[(r + 8) * SS_STRIDE + c + 4];
        }
        #pragma unroll
        for (int j = 0; j < 7; ++j) {
            int n = wn * 56 + j * 8 + g;
            int r = ks * 8 + t;
            b[j][0] = Wt[r * WS_STRIDE + n];
            b[j][1] = Wt[(r + 4) * WS_STRIDE + n];
        }
        #pragma unroll
        for (int j = 0; j < 7; ++j)
            mma_tf32(acc[j], a, b[j]);
    }

    {
        int r = row0 + wm * 16 + g;
        #pragma unroll
        for (int j = 0; j < 7; ++j) {
            int n = wn * 56 + j * 8 + 2 * t;
            *reinterpret_cast<uint2*>(&g_ttf[(size_t)r * E + n]) =
                make_uint2(f2tf32(acc[j][0]), f2tf32(acc[j][1]));
            *reinterpret_cast<uint2*>(&g_ttf[(size_t)(r + 8) * E + n]) =
                make_uint2(f2tf32(acc[j][2]), f2tf32(acc[j][3]));
        }
    }
}

// ---------------------------------------------------------------------------
// 3. Big tensor-core GEMM: part[split] = A[:, kc] @ t[kc, :]
//    A is raw fp32; mma.sync truncates to tf32 (RZ) in hardware.
// ---------------------------------------------------------------------------
__global__ void __launch_bounds__(256)
big_mm_mma(const float* __restrict__ A) {
    extern __shared__ uint32_t smem[];
    uint32_t* As = smem;                   // [2][128][AS_STRIDE]
    uint32_t* Bs = smem + 2 * AS_U32;      // [2][32][BS_STRIDE]

    const int tid = threadIdx.x;
    const int lane = tid & 31;
    const int wid = tid >> 5;
    const int wm = wid & 3;
    const int wn = wid >> 2;
    const int g = lane >> 2;
    const int t = lane & 3;
    const int row0 = blockIdx.x * 128;
    const int kbase = blockIdx.y * KCHUNK;

    float acc[2][7][4];
    #pragma unroll
    for (int i = 0; i < 2; ++i)
        #pragma unroll
        for (int j = 0; j < 7; ++j)
            #pragma unroll
            for (int k = 0; k < 4; ++k) acc[i][j][k] = 0.0f;

    auto stage = [&](int buf, int k0) {
        uint32_t* Ab = As + buf * AS_U32;
        uint32_t* Bb = Bs + buf * BS_U32;
        #pragma unroll
        for (int j = 0; j < 4; ++j) {
            int c = tid + j * 256;
            int r = c >> 3, cc = c & 7;
            uint32_t dst = smem_u32(&Ab[r * AS_STRIDE + cc * 4]);
            CP16(dst, &A[(size_t)(row0 + r) * B_SESS + k0 + cc * 4]);
        }
        #pragma unroll
        for (int j = 0; j < 4; ++j) {
            int c = tid + j * 256;
            if (c < 896) {
                int r = c / 28, cc = c % 28;
                uint32_t dst = smem_u32(&Bb[r * BS_STRIDE + cc * 4]);
                CP16(dst, &g_ttf[(size_t)(k0 + r) * E + cc * 4]);
            }
        }
    };

    auto compute = [&](int buf) {
        const uint32_t* A_ = As + buf * AS_U32;
        const uint32_t* B_ = Bs + buf * BS_U32;
        #pragma unroll
        for (int ks = 0; ks < 4; ++ks) {
            uint32_t a[2][4], b[7][2];
            #pragma unroll
            for (int i = 0; i < 2; ++i) {
                int r = wm * 32 + i * 16 + g;
                int c = ks * 8 + t;
                a[i][0] = A_[r * AS_STRIDE + c];
                a[i][1] = A_[(r + 8) * AS_STRIDE + c];
                a[i][2] = A_[r * AS_STRIDE + c + 4];
                a[i][3] = A_[(r + 8) * AS_STRIDE + c + 4];
            }
            #pragma unroll
            for (int j = 0; j < 7; ++j) {
                int n = wn * 56 + j * 8 + g;
                int r = ks * 8 + t;
                b[j][0] = B_[r * BS_STRIDE + n];
                b[j][1] = B_[(r + 4) * BS_STRIDE + n];
            }
            #pragma unroll
            for (int i = 0; i < 2; ++i)
                #pragma unroll
                for (int j = 0; j < 7; ++j)
                    mma_tf32(acc[i][j], a[i], b[j]);
        }
    };

    stage(0, kbase);
    CP_COMMIT();
    for (int s = 0; s < NSTAGE; ++s) {
        if (s + 1 < NSTAGE) {
            stage((s + 1) & 1, kbase + (s + 1) * BK);
            CP_COMMIT();
            CP_WAIT1();
        } else {
            CP_WAIT0();
        }
        __syncthreads();
        compute(s & 1);
        __syncthreads();
    }

    float* part = g_part + (size_t)blockIdx.y * B_SESS * E;
    #pragma unroll
    for (int i = 0; i < 2; ++i) {
        int r = row0 + wm * 32 + i * 16 + g;
        #pragma unroll
        for (int j = 0; j < 7; ++j) {
            int n = wn * 56 + j * 8 + 2 * t;
            *reinterpret_cast<float2*>(&part[(size_t)r * E + n]) =
                make_float2(acc[i][j][0], acc[i][j][1]);
            *reinterpret_cast<float2*>(&part[(size_t)(r + 8) * E + n]) =
                make_float2(acc[i][j][2], acc[i][j][3]);
        }
    }
}

// ---------------------------------------------------------------------------
// 4. Fused: split-K reduce + diag scale + L2-normalize + acc (+ final out)
//    One warp per row; block = 8 warps; grid = 512.
// ---------------------------------------------------------------------------
__global__ void reduce_norm_kernel(float* __restrict__ out, int last) {
    int warp = threadIdx.x >> 5;
    int lane = threadIdx.x & 31;
    int r = blockIdx.x * 8 + warp;

    float4 v = make_float4(0.f, 0.f, 0.f, 0.f);
    if (lane < E / 4) {
        #pragma unroll
        for (int c = 0; c < KSPLIT; ++c) {
            float4 p = *reinterpret_cast<const float4*>(
                &g_part[(size_t)c * B_SESS * E + (size_t)r * E + lane * 4]);
            v.x += p.x; v.y += p.y; v.z += p.z; v.w += p.w;
        }
        float d = g_d[r];
        v.x *= d; v.y *= d; v.z *= d; v.w *= d;
        *reinterpret_cast<float4*>(&g_s[(size_t)r * E + lane * 4]) = v;
    }
    float ss = v.x * v.x + v.y * v.y + v.z * v.z + v.w * v.w;
    #pragma unroll
    for (int o = 16; o; o >>= 1) ss += __shfl_xor_sync(0xffffffffu, ss, o);
    float f = 1.0f / fmaxf(sqrtf(ss), 1e-12f);
    if (lane < E / 4) {
        float4* arow = reinterpret_cast<float4*>(g_acc + (size_t)r * E);
        float4 a = arow[lane];
        a.x = fmaf(v.x, f, a.x);
        a.y = fmaf(v.y, f, a.y);
        a.z = fmaf(v.z, f, a.z);
        a.w = fmaf(v.w, f, a.w);
        arow[lane] = a;
        if (last) {
            float4 o4 = make_float4(a.x * 0.25f, a.y * 0.25f,
                                    a.z * 0.25f, a.w * 0.25f);
            *reinterpret_cast<float4*>(&out[(size_t)r * E + lane * 4]) = o4;
        }
    }
}

// ---------------------------------------------------------------------------
extern "C" void kernel_launch(void* const* d_in, const int* in_sizes, int n_in,
                              void* d_out, int out_size) {
    const float* emb   = (const float*)d_in[0];     // [100000,112]
    const float* D     = (const float*)d_in[1];     // [4096,4096]
    const float* A     = (const float*)d_in[2];     // [4096,4096]
    const float* slen  = (const float*)d_in[3];     // [4096,1]
    const float* Ws    = (const float*)d_in[4];     // [3,112,112]
    const int*   items = (const int*)d_in[5];       // [4096,200] int32
    float* out = (float*)d_out;

    cudaFuncSetAttribute(big_mm_mma, cudaFuncAttributeMaxDynamicSharedMemorySize,
                         SMEM_BYTES);
    cudaFuncSetAttribute(small_mm_tc, cudaFuncAttributeMaxDynamicSharedMemorySize,
                         SM2_BYTES);

    prep_kernel<<<NB_PREP, 448>>>(emb, items, slen, D);

    for (int l = 0; l < LAYERS; ++l) {
        small_mm_tc<<<128, 128, SM2_BYTES>>>(Ws + (size_t)l * E * E);
        big_mm_mma<<<dim3(B_SESS / 128, KSPLIT), 256, SMEM_BYTES>>>(A);
        reduce_norm_kernel<<<B_SESS / 8, 256>>>(out, l == LAYERS - 1);
    }
}